// round 17
// baseline (speedup 1.0000x reference)
#include <cuda_runtime.h>
#include <cuda_fp16.h>
#include <math.h>
#include <stdint.h>

// ---------------- problem dims ----------------
#define LSEQ 512
#define NB   64
#define IDIM 1024
#define HDIM 1024
#define KTOT 2048
#define NBLK 128
#define HC   8
#define ZC   32
#define NGRP 4

// shared rows: 512B data + 16B pad (33 x 16B units -> conflict-free ldsm)
#define LDB     528
#define B_SPLIT (32 * LDB)              // 16896 per group (B resident)
#define B_RES   (NGRP * B_SPLIT)        // 67584
#define A_GRP   (64 * LDB)              // 33792 per group (A fully resident)
#define A_OFF   B_RES
#define SMEM_P  (B_RES + NGRP * A_GRP)  // 202752

// zx precompute GEMM tiling (single-term fp16)
#define P_LDA 144
#define P_TILE (128 * P_LDA)            // 18432
#define P_STG  (2 * P_TILE)             // 36864
#define P_SMEM (2 * P_STG)              // 73728

// ---------------- device scratch ----------------
__device__ __half gWx[NBLK * ZC * IDIM];    // fp16 W_ih block-major (zx path)
__device__ __half gV [NBLK * ZC * HDIM];    // fp16 W_hh block-major (recurrent)
__device__ float  gB[4 * HDIM];
__device__ __half gX[(size_t)LSEQ * NB * IDIM];   // fp16 x
__device__ __half gH[2][NB * HDIM];         // h ping-pong fp16
__device__ float  g_c [NB * HDIM];
__device__ float  g_hf[NB * HDIM];
__device__ float  g_zx[(size_t)LSEQ * NBLK * 64 * 32];
__device__ unsigned g_flag[NBLK];           // per-block step flags (grid barrier)

// ---------------- helpers ----------------
__device__ __forceinline__ uint32_t smem_u32(const void* p) {
    uint32_t a;
    asm("{ .reg .u64 t; cvta.to.shared.u64 t, %1; cvt.u32.u64 %0, t; }" : "=r"(a) : "l"(p));
    return a;
}
__device__ __forceinline__ void cp16(uint32_t dst, const void* src) {
    asm volatile("cp.async.cg.shared.global [%0], [%1], 16;"
                 :: "r"(dst), "l"(__cvta_generic_to_global(src)));
}
__device__ __forceinline__ void ldsm4(uint32_t* r, uint32_t a) {
    asm volatile("ldmatrix.sync.aligned.m8n8.x4.shared.b16 {%0,%1,%2,%3}, [%4];"
                 : "=r"(r[0]), "=r"(r[1]), "=r"(r[2]), "=r"(r[3]) : "r"(a));
}
__device__ __forceinline__ void mma_f16(float* c, const uint32_t* a,
                                        uint32_t b0, uint32_t b1) {
    asm volatile(
        "mma.sync.aligned.m16n8k16.row.col.f32.f16.f16.f32 "
        "{%0,%1,%2,%3},{%4,%5,%6,%7},{%8,%9},{%0,%1,%2,%3};"
        : "+f"(c[0]), "+f"(c[1]), "+f"(c[2]), "+f"(c[3])
        : "r"(a[0]), "r"(a[1]), "r"(a[2]), "r"(a[3]), "r"(b0), "r"(b1));
}

// ---------------- prep kernels ----------------
__global__ void reset_bar() { if (threadIdx.x < NBLK) g_flag[threadIdx.x] = 0; }

__global__ __launch_bounds__(256) void prep_w(
    const float* __restrict__ Wih, const float* __restrict__ Whh,
    const float* __restrict__ bih, const float* __restrict__ bhh)
{
    int d  = blockIdx.x * 256 + threadIdx.x;   // 0 .. 8388607
    int b  = d >> 16;
    int rr = (d >> 11) & 31;
    int k  = d & 2047;
    int zc = ((rr >> 3) << 10) + b * HC + (rr & 7);
    if (k < IDIM) {
        gWx[(b * ZC + rr) * IDIM + k] = __float2half(Wih[zc * IDIM + k]);
    } else {
        gV[(b * ZC + rr) * HDIM + (k - IDIM)] = __float2half(Whh[zc * HDIM + (k - IDIM)]);
    }
    if (d < 4 * HDIM) gB[d] = bih[d] + bhh[d];
}

__global__ __launch_bounds__(256) void prep_x(const float* __restrict__ x)
{
    size_t i = ((size_t)blockIdx.x * 256 + threadIdx.x) * 4;
    float4 v = *reinterpret_cast<const float4*>(x + i);
    *reinterpret_cast<__half2*>(gX + i)     = __floats2half2_rn(v.x, v.y);
    *reinterpret_cast<__half2*>(gX + i + 2) = __floats2half2_rn(v.z, v.w);
}

__global__ __launch_bounds__(256) void init_h(
    const float* __restrict__ h0, const float* __restrict__ c0)
{
    int idx = blockIdx.x * 256 + threadIdx.x;
    gH[0][idx] = __float2half(h0[idx]);
    g_c[idx] = c0[idx];
}

// ---------------- zx precompute: zx = x @ W_ih^T (single-term fp16) ----------------
__global__ __launch_bounds__(256, 1) void zx_gemm()
{
    extern __shared__ char sm[];
    const uint32_t sb = smem_u32(sm);
    const int tid = threadIdx.x;
    const int w   = tid >> 5;
    const int l   = tid & 31;
    const int wm  = w >> 2;
    const int wn  = w & 3;
    const int bn  = blockIdx.x;
    const int bm  = blockIdx.y;

    const __half* __restrict__ xp = gX  + (size_t)bm * 128 * IDIM;
    const __half* __restrict__ wp = gWx + (size_t)bn * 128 * IDIM;

    float acc[4][4][4] = {};

    auto load_chunk = [&](int ch, int pb) {
        const uint32_t st = sb + pb * P_STG;
        const int k0 = ch * 64;
        #pragma unroll
        for (int i = 0; i < 4; i++) {
            int s = tid + i * 256, r = s >> 3, sg = s & 7;
            cp16(st + r * P_LDA + sg * 16, xp + (size_t)r * IDIM + k0 + sg * 8);
        }
        #pragma unroll
        for (int i = 0; i < 4; i++) {
            int s = tid + i * 256, r = s >> 3, sg = s & 7;
            cp16(st + P_TILE + r * P_LDA + sg * 16, wp + (size_t)r * IDIM + k0 + sg * 8);
        }
        asm volatile("cp.async.commit_group;" ::: "memory");
    };

    const uint32_t rowA = wm * 64 + (l & 7) + ((l >> 3) & 1) * 8;
    const uint32_t acol = (l >> 4) * 16;
    const uint32_t rowB = wn * 32 + (l & 7) + ((l >> 4) & 1) * 8;
    const uint32_t bcol = ((l >> 3) & 1) * 16;

    load_chunk(0, 0);

    for (int ch = 0; ch < 16; ch++) {
        asm volatile("cp.async.wait_group 0;" ::: "memory");
        __syncthreads();
        if (ch + 1 < 16) load_chunk(ch + 1, (ch + 1) & 1);

        const uint32_t st  = sb + (ch & 1) * P_STG;
        const uint32_t aHb = st + rowA * P_LDA + acol;
        const uint32_t bHb = st + P_TILE + rowB * P_LDA + bcol;

        #pragma unroll
        for (int ks = 0; ks < 4; ks++) {
            const uint32_t ko = ks * 32;
            uint32_t ah[4][4], bh[2][4];
            #pragma unroll
            for (int mt = 0; mt < 4; mt++)
                ldsm4(ah[mt], aHb + mt * 16 * P_LDA + ko);
            ldsm4(bh[0], bHb + ko);
            ldsm4(bh[1], bHb + 16 * P_LDA + ko);
            #pragma unroll
            for (int mt = 0; mt < 4; mt++)
                #pragma unroll
                for (int nt = 0; nt < 4; nt++)
                    mma_f16(acc[mt][nt], ah[mt], bh[nt >> 1][(nt & 1) * 2],
                            bh[nt >> 1][(nt & 1) * 2 + 1]);
        }
    }

    // write zx in step-tile order: [t][blk][r64][c32]
    #pragma unroll
    for (int mt = 0; mt < 4; mt++)
        #pragma unroll
        for (int nt = 0; nt < 4; nt++)
            #pragma unroll
            for (int j = 0; j < 4; j++) {
                int m  = wm * 64 + mt * 16 + (l >> 2) + (j >> 1) * 8;
                int cc = wn * 32 + nt * 8 + (l & 3) * 2 + (j & 1);
                int t  = blockIdx.y * 2 + (m >> 6);
                int r  = m & 63;
                int blk = bn * 4 + (cc >> 5);
                int c   = cc & 31;
                g_zx[(((size_t)t * NBLK + blk) * 64 + r) * 32 + c] = acc[mt][nt][j];
            }
}

// ---------------- persistent recurrent kernel (single-term fp16) ----------------
__global__ __launch_bounds__(256, 1) void lstm_persist()
{
    extern __shared__ char sm[];
    const uint32_t sb = smem_u32(sm);
    const int tid = threadIdx.x;
    const int w   = tid >> 5, l = tid & 31;
    const int g   = w >> 1,  wg = w & 1;
    const int gt  = tid & 63;
    const int blk = blockIdx.x;
    const int jh0 = blk * HC;

    const __half* __restrict__ Vp = gV + (size_t)blk * ZC * HDIM;

    // ---- one-time: resident B (this group's K quarter) ----
    const uint32_t bgrp = sb + g * B_SPLIT;
    {
        const int kb = g * 256;
        #pragma unroll
        for (int j = 0; j < 16; j++) {
            int idx = gt + j * 64;
            int r = idx >> 5, sg = idx & 31;
            cp16(bgrp + r * LDB + sg * 16, Vp + (size_t)r * HDIM + kb + sg * 8);
        }
        asm volatile("cp.async.commit_group;" ::: "memory");
    }

    const uint32_t agrp = sb + A_OFF + g * A_GRP;
    const uint32_t rowA = wg * 32 + (l & 7) + ((l >> 3) & 1) * 8;
    const uint32_t acol = (l >> 4) * 16;
    const uint32_t rowB = (l & 7) + ((l >> 4) & 1) * 8;
    const uint32_t bcol = ((l >> 3) & 1) * 16;
    const uint32_t aHb0 = agrp + rowA * LDB + acol;
    const uint32_t bHb0 = bgrp + rowB * LDB + bcol;

    // ---- per-thread epilogue state ----
    int   erow[2], ecol[2];
    float bia[2][4], creg[2];
    #pragma unroll
    for (int u = 0; u < 2; u++) {
        int idx = tid * 2 + u;
        erow[u] = idx >> 3;
        ecol[u] = jh0 + (idx & 7);
        bia[u][0] = gB[ecol[u]];
        bia[u][1] = gB[1024 + ecol[u]];
        bia[u][2] = gB[2048 + ecol[u]];
        bia[u][3] = gB[3072 + ecol[u]];
        creg[u] = g_c[erow[u] * HDIM + ecol[u]];
    }

    #pragma unroll 1
    for (int s = 0; s < LSEQ; s++) {
        const __half* __restrict__ Hp = gH[s & 1];

        // zx prefetch into registers
        const float* zxp = g_zx + ((size_t)s * NBLK + blk) * 64 * 32;
        float zxr[2][4];
        #pragma unroll
        for (int u = 0; u < 2; u++) {
            int base = erow[u] * 32 + (ecol[u] - jh0);
            zxr[u][0] = zxp[base];
            zxr[u][1] = zxp[base + 8];
            zxr[u][2] = zxp[base + 16];
            zxr[u][3] = zxp[base + 24];
        }

        // load A (64 rows x 256 k fp16, fully resident) in 2 halves
        auto load_half = [&](int h) {
            const int kb = g * 256 + h * 128;
            #pragma unroll
            for (int j = 0; j < 16; j++) {        // 1024 segs / 64 thr
                int e = gt + j * 64;
                int r = e >> 4, sg = e & 15;
                cp16(agrp + r * LDB + h * 256 + sg * 16,
                     Hp + (size_t)r * HDIM + kb + sg * 8);
            }
            asm volatile("cp.async.commit_group;" ::: "memory");
        };
        load_half(0);
        load_half(1);

        float acc[2][4][4] = {};

        #pragma unroll
        for (int half = 0; half < 2; half++) {
            if (half == 0) asm volatile("cp.async.wait_group 1;" ::: "memory");
            else           asm volatile("cp.async.wait_group 0;" ::: "memory");
            asm volatile("bar.sync %0, %1;" :: "r"(g + 1), "r"(64) : "memory");

            #pragma unroll
            for (int i = half * 4; i < half * 4 + 4; i++) {
                #pragma unroll
                for (int ks = 0; ks < 2; ks++) {
                    const uint32_t ko = i * 64 + ks * 32;
                    uint32_t ah[2][4], bh[2][4];
                    ldsm4(ah[0], aHb0 + ko);
                    ldsm4(ah[1], aHb0 + 16 * LDB + ko);
                    ldsm4(bh[0], bHb0 + ko);
                    ldsm4(bh[1], bHb0 + 16 * LDB + ko);
                    #pragma unroll
                    for (int mt = 0; mt < 2; mt++)
                        #pragma unroll
                        for (int nt = 0; nt < 4; nt++)
                            mma_f16(acc[mt][nt], ah[mt], bh[nt >> 1][(nt & 1) * 2],
                                    bh[nt >> 1][(nt & 1) * 2 + 1]);
                }
            }
        }

        // ---- epilogue: partials -> smem (overlay A region) -> gates ----
        __syncthreads();
        float* zs = (float*)(sm + A_OFF);          // [4][64][33]
        const int zb = g * (64 * 33);
        #pragma unroll
        for (int mt = 0; mt < 2; mt++)
            #pragma unroll
            for (int nt = 0; nt < 4; nt++)
                #pragma unroll
                for (int j = 0; j < 4; j++) {
                    int r = wg * 32 + mt * 16 + (l >> 2) + (j >> 1) * 8;
                    int c = nt * 8 + (l & 3) * 2 + (j & 1);
                    zs[zb + r * 33 + c] = acc[mt][nt][j];
                }
        __syncthreads();

        const int wrb = (s + 1) & 1;
        #pragma unroll
        for (int u = 0; u < 2; u++) {
            int r = erow[u], col = ecol[u], hid = col - jh0;
            float zi = bia[u][0] + zxr[u][0];
            float zf = bia[u][1] + zxr[u][1];
            float zg = bia[u][2] + zxr[u][2];
            float zo = bia[u][3] + zxr[u][3];
            #pragma unroll
            for (int q = 0; q < 4; q++) {
                const float* p = zs + q * (64 * 33) + r * 33;
                zi += p[hid]; zf += p[8 + hid]; zg += p[16 + hid]; zo += p[24 + hid];
            }
            float ig = 1.0f / (1.0f + expf(-zi));
            float fg = 1.0f / (1.0f + expf(-zf));
            float og = 1.0f / (1.0f + expf(-zo));
            float gg = tanhf(zg);
            creg[u] = fg * creg[u] + ig * gg;
            float hv = og * tanhf(creg[u]);
            gH[wrb][r * HDIM + col] = __float2half(hv);
            if (s == LSEQ - 1) {
                g_hf[r * HDIM + col] = hv;
                g_c [r * HDIM + col] = creg[u];
            }
        }

        // ---- grid barrier: per-block release flags + parallel acquire poll ----
        if (s + 1 < LSEQ) {
            __syncthreads();   // all threads' h writes ordered before release
            if (tid == 0)
                asm volatile("st.release.gpu.u32 [%0], %1;"
                             :: "l"(&g_flag[blk]), "r"((unsigned)(s + 1)) : "memory");
            const unsigned target = (unsigned)(s + 1);
            int ok;
            do {
                unsigned v = target;
                if (tid < NBLK)
                    asm volatile("ld.acquire.gpu.u32 %0, [%1];"
                                 : "=r"(v) : "l"(&g_flag[tid]) : "memory");
                ok = (v >= target);
            } while (!__syncthreads_and(ok));
        }
    }
}

// ---------------- final projection ----------------
__global__ __launch_bounds__(128) void out_proj(
    const float* __restrict__ Wout, const float* __restrict__ bout,
    float* __restrict__ y)
{
    int n = blockIdx.y;
    int i = blockIdx.x * 128 + threadIdx.x;
    __shared__ float hs[HDIM];
    for (int k = threadIdx.x; k < HDIM; k += 128) hs[k] = g_hf[n * HDIM + k];
    __syncthreads();
    float acc = bout[i];
    const float* wrow = Wout + (size_t)i * HDIM;
    #pragma unroll 8
    for (int k = 0; k < HDIM; k++) acc += hs[k] * wrow[k];
    y[n * IDIM + i] = acc;
}

__global__ void copy_hc(float* __restrict__ out)
{
    int idx = blockIdx.x * 256 + threadIdx.x;
    out[NB * IDIM + idx]             = g_hf[idx];
    out[NB * IDIM + NB * HDIM + idx] = g_c[idx];
}

// ---------------- launch ----------------
extern "C" void kernel_launch(void* const* d_in, const int* in_sizes, int n_in,
                              void* d_out, int out_size)
{
    const float* x    = (const float*)d_in[0];
    const float* h0   = (const float*)d_in[1];
    const float* c0   = (const float*)d_in[2];
    const float* Wih  = (const float*)d_in[3];
    const float* Whh  = (const float*)d_in[4];
    const float* bih  = (const float*)d_in[5];
    const float* bhh  = (const float*)d_in[6];
    const float* Wout = (const float*)d_in[7];
    const float* bout = (const float*)d_in[8];
    float* out = (float*)d_out;

    cudaFuncSetAttribute(lstm_persist,
                         cudaFuncAttributeMaxDynamicSharedMemorySize, SMEM_P);
    cudaFuncSetAttribute(zx_gemm,
                         cudaFuncAttributeMaxDynamicSharedMemorySize, P_SMEM);

    reset_bar<<<1, 128>>>();
    prep_w<<<(NBLK * ZC * KTOT) / 256, 256>>>(Wih, Whh, bih, bhh);
    prep_x<<<(int)(((size_t)LSEQ * NB * IDIM) / 1024), 256>>>(x);
    init_h<<<(NB * HDIM) / 256, 256>>>(h0, c0);

    dim3 pg(32, 256);
    zx_gemm<<<pg, 256, P_SMEM>>>();

    lstm_persist<<<NBLK, 256, SMEM_P>>>();

    dim3 yg(IDIM / 128, NB);
    out_proj<<<yg, 128>>>(Wout, bout, out);
    copy_hc<<<(NB * HDIM) / 256, 256>>>(out);
}